// round 12
// baseline (speedup 1.0000x reference)
#include <cuda_runtime.h>
#include <cstdint>

// Single fused persistent kernel: Linear (16x3 GEMV) + 3x channel-weighted
// reductions. Uniform 32KB tiles (8 strided float4 loads/thread for every
// region) expressed with runtime parameters so tiles can be SOFTWARE
// PIPELINED across region boundaries: tile k+1's loads issue before tile k's
// barrier, hiding the per-tile DRAM latency bubble under the combine/store.
// Two-ahead tile-id prefetch via parity-buffered s_tile[2]; parity-buffered
// partials; streaming cache hints; self-resetting counters for graph replay.
// Inputs: 0 gap[16,448], 1 out1[16,64,15,64,64], 2 out2[16,128,8,32,32],
//         3 out3[16,256,4,16,16], 4 weight[3,448], 5 bias[3]
// Output: fc[48] | vis1[983040] | vis2[131072] | vis3[16384]  (float)

#define BATCH 16
#define KDIM  448

#define SV1 15360   // spatial float4s per batch image
#define SV2 2048
#define SV3 256

// uniform 32KB tiles
#define NT3 512     // 4096 f4 outs / 8
#define NT2 2048    // 32768 f4 outs / 16
#define NT1 7680    // 245760 f4 outs / 32
#define T3_BEG 1
#define T2_BEG (1 + NT3)
#define T1_BEG (1 + NT3 + NT2)
#define TOTAL_TILES (1 + NT3 + NT2 + NT1)   // 10241

#define OUT_FC 0
#define OUT_V1 48
#define OUT_V2 (48 + 983040)
#define OUT_V3 (48 + 983040 + 131072)

#define GRID_MAIN 444   // 3 blocks/SM * 148 SMs — single wave at occ 3

__device__ int g_ctr  = GRID_MAIN;   // tiles 0..443 statically assigned
__device__ int g_done = 0;

__device__ __forceinline__ float4 ldcs4(const float4* p) {
    float4 v;
    asm volatile("ld.global.cs.v4.f32 {%0,%1,%2,%3}, [%4];"
                 : "=f"(v.x), "=f"(v.y), "=f"(v.z), "=f"(v.w) : "l"(p));
    return v;
}
__device__ __forceinline__ void stcs4(float4* p, float4 v) {
    asm volatile("st.global.cs.v4.f32 [%0], {%1,%2,%3,%4};"
                 :: "l"(p), "f"(v.x), "f"(v.y), "f"(v.z), "f"(v.w));
}

struct TileP {
    const float4* in;    // this thread's first load address
    float4*       dstp;  // this thread's output slot (used when g==0)
    const float*  wg;    // this thread's 8 weights (smem)
    int o, g, OUTS, G, stride;
};

__device__ __forceinline__ TileP tile_params(
    int t, int tid,
    const float4* s1, const float4* s2, const float4* s3,
    float4* d1, float4* d2, float4* d3, const float* wsm)
{
    int rel, OUTS, sh, G, SV, CSV, woff;
    const float4* src; float4* dst;
    if (t >= T1_BEG) {
        rel = t - T1_BEG; OUTS = 32; sh = 5; G = 8;
        SV = SV1; CSV = 64 * SV1; src = s1; dst = d1; woff = 0;
    } else if (t >= T2_BEG) {
        rel = t - T2_BEG; OUTS = 16; sh = 4; G = 16;
        SV = SV2; CSV = 128 * SV2; src = s2; dst = d2; woff = 64;
    } else {
        rel = t - T3_BEG; OUTS = 8;  sh = 3; G = 32;
        SV = SV3; CSV = 256 * SV3; src = s3; dst = d3; woff = 192;
    }
    TileP p;
    int o = tid & (OUTS - 1);
    int g = tid >> sh;
    int v = rel * OUTS + o;
    int b = v / SV;
    int sv = v - b * SV;
    p.in     = src + b * CSV + sv + (g * 8) * SV;
    p.dstp   = dst + v;
    p.wg     = wsm + woff + g * 8;
    p.o = o; p.g = g; p.OUTS = OUTS; p.G = G; p.stride = SV;
    return p;
}

__global__ void __launch_bounds__(256, 3)
fused_all_kernel(const float* __restrict__ gap,
                 const float* __restrict__ out1,
                 const float* __restrict__ out2,
                 const float* __restrict__ out3,
                 const float* __restrict__ weight,
                 const float* __restrict__ bias,
                 float* __restrict__ dout)
{
    __shared__ float  wsm[KDIM];     // combined 0.5*(w0+w1)
    __shared__ float4 part[2][248];  // parity double-buffer (max (G-1)*OUTS)
    __shared__ int    s_tile[2];     // parity double-buffer for tile ids

    int tid = threadIdx.x;
    for (int k = tid; k < KDIM; k += 256)
        wsm[k] = 0.5f * (weight[k] + weight[KDIM + k]);

    const float4* s1 = reinterpret_cast<const float4*>(out1);
    const float4* s2 = reinterpret_cast<const float4*>(out2);
    const float4* s3 = reinterpret_cast<const float4*>(out3);
    float4* d1 = reinterpret_cast<float4*>(dout + OUT_V1);
    float4* d2 = reinterpret_cast<float4*>(dout + OUT_V2);
    float4* d3 = reinterpret_cast<float4*>(dout + OUT_V3);

    // ---- prologue: establish (t = current tile, tn = next tile) ----
    if (tid == 0) s_tile[0] = atomicAdd(&g_ctr, 1);
    __syncthreads();                 // publishes s_tile[0] AND wsm

    int t, tn, sl;
    if (blockIdx.x == 0) {
        // fc tile: fc[b][j] = gap[b] . weight[j] + bias[j]  (48 outputs)
        if (tid < BATCH * 3) {
            int b = tid / 3, j = tid % 3;
            const float4* g4 = reinterpret_cast<const float4*>(gap + b * KDIM);
            const float4* w4 = reinterpret_cast<const float4*>(weight + j * KDIM);
            float acc = 0.f;
#pragma unroll 8
            for (int k = 0; k < KDIM / 4; ++k) {
                float4 a = g4[k], w = w4[k];
                acc += a.x * w.x + a.y * w.y + a.z * w.z + a.w * w.w;
            }
            dout[OUT_FC + tid] = acc + bias[j];
        }
        t = s_tile[0];
        if (tid == 0) s_tile[1] = atomicAdd(&g_ctr, 1);
        __syncthreads();
        tn = s_tile[1];
        sl = 0;
    } else {
        t  = blockIdx.x;             // static first tile (1..443 are data tiles)
        tn = s_tile[0];
        sl = 1;
    }

    TileP P = tile_params(t, tid, s1, s2, s3, d1, d2, d3, wsm);
    float4 X0 = ldcs4(P.in + 0 * P.stride);
    float4 X1 = ldcs4(P.in + 1 * P.stride);
    float4 X2 = ldcs4(P.in + 2 * P.stride);
    float4 X3 = ldcs4(P.in + 3 * P.stride);
    float4 X4 = ldcs4(P.in + 4 * P.stride);
    float4 X5 = ldcs4(P.in + 5 * P.stride);
    float4 X6 = ldcs4(P.in + 6 * P.stride);
    float4 X7 = ldcs4(P.in + 7 * P.stride);

    int par = 0;
    for (;;) {
        // prefetch tile id two ahead (published by this iteration's barrier)
        if (tid == 0) s_tile[sl] = atomicAdd(&g_ctr, 1);

        // consume current tile's registers
        float w0 = P.wg[0], w1 = P.wg[1], w2 = P.wg[2], w3 = P.wg[3];
        float w4 = P.wg[4], w5 = P.wg[5], w6 = P.wg[6], w7 = P.wg[7];
        float4 a0, a1;
        a0.x  = w0 * X0.x; a0.y  = w0 * X0.y; a0.z  = w0 * X0.z; a0.w  = w0 * X0.w;
        a1.x  = w1 * X1.x; a1.y  = w1 * X1.y; a1.z  = w1 * X1.z; a1.w  = w1 * X1.w;
        a0.x += w2 * X2.x; a0.y += w2 * X2.y; a0.z += w2 * X2.z; a0.w += w2 * X2.w;
        a1.x += w3 * X3.x; a1.y += w3 * X3.y; a1.z += w3 * X3.z; a1.w += w3 * X3.w;
        a0.x += w4 * X4.x; a0.y += w4 * X4.y; a0.z += w4 * X4.z; a0.w += w4 * X4.w;
        a1.x += w5 * X5.x; a1.y += w5 * X5.y; a1.z += w5 * X5.z; a1.w += w5 * X5.w;
        a0.x += w6 * X6.x; a0.y += w6 * X6.y; a0.z += w6 * X6.z; a0.w += w6 * X6.w;
        a1.x += w7 * X7.x; a1.y += w7 * X7.y; a1.z += w7 * X7.z; a1.w += w7 * X7.w;
        float4 acc = make_float4(a0.x + a1.x, a0.y + a1.y, a0.z + a1.z, a0.w + a1.w);

        // issue NEXT tile's loads now — they fly during combine/store/barrier
        bool have_next = (tn < TOTAL_TILES);
        TileP Pn;
        if (have_next) {
            Pn = tile_params(tn, tid, s1, s2, s3, d1, d2, d3, wsm);
            X0 = ldcs4(Pn.in + 0 * Pn.stride);
            X1 = ldcs4(Pn.in + 1 * Pn.stride);
            X2 = ldcs4(Pn.in + 2 * Pn.stride);
            X3 = ldcs4(Pn.in + 3 * Pn.stride);
            X4 = ldcs4(Pn.in + 4 * Pn.stride);
            X5 = ldcs4(Pn.in + 5 * Pn.stride);
            X6 = ldcs4(Pn.in + 6 * Pn.stride);
            X7 = ldcs4(Pn.in + 7 * Pn.stride);
        }

        // combine current tile across channel groups
        if (P.g != 0) part[par][(P.g - 1) * P.OUTS + P.o] = acc;
        __syncthreads();             // orders part writes AND s_tile[sl]
        if (P.g == 0) {
            for (int j = 0; j < P.G - 1; ++j) {
                float4 q = part[par][j * P.OUTS + P.o];
                acc.x += q.x; acc.y += q.y; acc.z += q.z; acc.w += q.w;
            }
            stcs4(P.dstp, acc);
        }
        par ^= 1;

        if (!have_next) break;
        P  = Pn;
        tn = s_tile[sl];
        sl ^= 1;
    }

    // self-reset: last block out restores counters for the next graph replay.
    if (tid == 0) {
        __threadfence();
        int d = atomicAdd(&g_done, 1);
        if (d == GRID_MAIN - 1) {
            g_ctr  = GRID_MAIN;
            g_done = 0;
            __threadfence();
        }
    }
}

extern "C" void kernel_launch(void* const* d_in, const int* in_sizes, int n_in,
                              void* d_out, int out_size)
{
    const float* gap    = (const float*)d_in[0];
    const float* out1   = (const float*)d_in[1];
    const float* out2   = (const float*)d_in[2];
    const float* out3   = (const float*)d_in[3];
    const float* weight = (const float*)d_in[4];
    const float* bias   = (const float*)d_in[5];
    float* dout = (float*)d_out;

    fused_all_kernel<<<GRID_MAIN, 256>>>(gap, out1, out2, out3, weight, bias, dout);
}

// round 13
// speedup vs baseline: 1.0447x; 1.0447x over previous
#include <cuda_runtime.h>
#include <cstdint>

// Single fused persistent kernel: Linear (16x3 GEMV) + 3x channel-weighted
// reductions. Cost-uniform 32KB tiles (r1: 32 outs x C64, r2: 16 outs x C128,
// r3: 8 outs x C256) -> every tile is 8 strided float4 loads per thread; the
// fine granularity shrinks the end-of-kernel drain tail ~4x. One sync per
// tile (combine sync also publishes prefetched tile id); parity-buffered
// partials; streaming cache hints; self-resetting counters for graph replay.
// (Measured-best configuration: R11, 51.7us.)
// Inputs: 0 gap[16,448], 1 out1[16,64,15,64,64], 2 out2[16,128,8,32,32],
//         3 out3[16,256,4,16,16], 4 weight[3,448], 5 bias[3]
// Output: fc[48] | vis1[983040] | vis2[131072] | vis3[16384]  (float)

#define BATCH 16
#define KDIM  448

#define SV1 15360   // spatial float4s per batch image
#define SV2 2048
#define SV3 256

// uniform 32KB tiles
#define NT3 512     // 4096 f4 outs / 8
#define NT2 2048    // 32768 f4 outs / 16
#define NT1 7680    // 245760 f4 outs / 32
#define T3_BEG 1
#define T2_BEG (1 + NT3)
#define T1_BEG (1 + NT3 + NT2)
#define TOTAL_TILES (1 + NT3 + NT2 + NT1)   // 10241

#define OUT_FC 0
#define OUT_V1 48
#define OUT_V2 (48 + 983040)
#define OUT_V3 (48 + 983040 + 131072)

#define GRID_MAIN 592   // 4 blocks/SM * 148 SMs — single resident wave

__device__ int g_ctr  = GRID_MAIN;   // tiles 0..591 statically assigned
__device__ int g_done = 0;

__device__ __forceinline__ float4 ldcs4(const float4* p) {
    float4 v;
    asm volatile("ld.global.cs.v4.f32 {%0,%1,%2,%3}, [%4];"
                 : "=f"(v.x), "=f"(v.y), "=f"(v.z), "=f"(v.w) : "l"(p));
    return v;
}
__device__ __forceinline__ void stcs4(float4* p, float4 v) {
    asm volatile("st.global.cs.v4.f32 [%0], {%1,%2,%3,%4};"
                 :: "l"(p), "f"(v.x), "f"(v.y), "f"(v.z), "f"(v.w));
}

// Uniform tile: OUTS float4 outputs, G = 256/OUTS channel groups, CC = C/G = 8
// strided loads per thread. Internal __syncthreads publishes tid0's s_tile.
template<int C, int OUTS, int SV>
__device__ __forceinline__ void do_tile(const float* __restrict__ src,
                                        float* __restrict__ dst,
                                        const float* __restrict__ wsm,
                                        float4* __restrict__ part,  // [256-OUTS]
                                        int lt)
{
    constexpr int G  = 256 / OUTS;
    constexpr int CC = C / G;          // == 8 for all regions
    static_assert(CC == 8, "uniform tiles expect 8 loads/thread");

    int tid = threadIdx.x;
    int o = tid % OUTS;
    int g = tid / OUTS;
    int v = lt * OUTS + o;             // float4 output index within region
    int b = v / SV;
    int sv = v - b * SV;

    const float4* in = reinterpret_cast<const float4*>(src)
                       + b * (C * SV) + sv + (g * CC) * SV;
    const float* wg = wsm + g * CC;

    float4 x0 = ldcs4(in + 0 * SV);
    float4 x1 = ldcs4(in + 1 * SV);
    float4 x2 = ldcs4(in + 2 * SV);
    float4 x3 = ldcs4(in + 3 * SV);
    float4 x4 = ldcs4(in + 4 * SV);
    float4 x5 = ldcs4(in + 5 * SV);
    float4 x6 = ldcs4(in + 6 * SV);
    float4 x7 = ldcs4(in + 7 * SV);
    float w0 = wg[0], w1 = wg[1], w2 = wg[2], w3 = wg[3];
    float w4 = wg[4], w5 = wg[5], w6 = wg[6], w7 = wg[7];

    float4 a0, a1;
    a0.x = w0 * x0.x; a0.y = w0 * x0.y; a0.z = w0 * x0.z; a0.w = w0 * x0.w;
    a1.x = w1 * x1.x; a1.y = w1 * x1.y; a1.z = w1 * x1.z; a1.w = w1 * x1.w;
    a0.x += w2 * x2.x; a0.y += w2 * x2.y; a0.z += w2 * x2.z; a0.w += w2 * x2.w;
    a1.x += w3 * x3.x; a1.y += w3 * x3.y; a1.z += w3 * x3.z; a1.w += w3 * x3.w;
    a0.x += w4 * x4.x; a0.y += w4 * x4.y; a0.z += w4 * x4.z; a0.w += w4 * x4.w;
    a1.x += w5 * x5.x; a1.y += w5 * x5.y; a1.z += w5 * x5.z; a1.w += w5 * x5.w;
    a0.x += w6 * x6.x; a0.y += w6 * x6.y; a0.z += w6 * x6.z; a0.w += w6 * x6.w;
    a1.x += w7 * x7.x; a1.y += w7 * x7.y; a1.z += w7 * x7.z; a1.w += w7 * x7.w;
    float4 acc = make_float4(a0.x + a1.x, a0.y + a1.y, a0.z + a1.z, a0.w + a1.w);

    if (g != 0) part[(g - 1) * OUTS + o] = acc;
    __syncthreads();            // orders part writes AND tid0's s_tile prefetch
    if (g == 0) {
#pragma unroll
        for (int j = 0; j < G - 1; ++j) {
            float4 p = part[j * OUTS + o];
            acc.x += p.x; acc.y += p.y; acc.z += p.z; acc.w += p.w;
        }
        stcs4(reinterpret_cast<float4*>(dst) + v, acc);
    }
}

__global__ void __launch_bounds__(256, 4)
fused_all_kernel(const float* __restrict__ gap,
                 const float* __restrict__ out1,
                 const float* __restrict__ out2,
                 const float* __restrict__ out3,
                 const float* __restrict__ weight,
                 const float* __restrict__ bias,
                 float* __restrict__ dout)
{
    __shared__ float  wsm[KDIM];     // combined 0.5*(w0+w1)
    __shared__ float4 part[2][248];  // parity double-buffer (max G-1=31 x 8)
    __shared__ int    s_tile;

    int tid = threadIdx.x;
    for (int k = tid; k < KDIM; k += 256)
        wsm[k] = 0.5f * (weight[k] + weight[KDIM + k]);
    __syncthreads();                 // wsm visible before first tile

    int t = blockIdx.x;              // static first tile (no startup storm)
    int it = 0;                      // parity for part[] reuse safety
    while (t < TOTAL_TILES) {
        if (tid == 0) s_tile = atomicAdd(&g_ctr, 1);
        float4* pb = part[it & 1];

        if (t >= T1_BEG) {
            do_tile<64, 32, SV1>(out1, dout + OUT_V1, wsm, pb, t - T1_BEG);
        } else if (t >= T2_BEG) {
            do_tile<128, 16, SV2>(out2, dout + OUT_V2, wsm + 64, pb, t - T2_BEG);
        } else if (t >= T3_BEG) {
            do_tile<256, 8, SV3>(out3, dout + OUT_V3, wsm + 192, pb, t - T3_BEG);
        } else {
            // fc tile: fc[b][j] = gap[b] . weight[j] + bias[j]  (48 outputs)
            if (tid < BATCH * 3) {
                int b = tid / 3, j = tid % 3;
                const float4* g4 = reinterpret_cast<const float4*>(gap + b * KDIM);
                const float4* w4 = reinterpret_cast<const float4*>(weight + j * KDIM);
                float acc = 0.f;
#pragma unroll 8
                for (int k = 0; k < KDIM / 4; ++k) {
                    float4 a = g4[k], w = w4[k];
                    acc += a.x * w.x + a.y * w.y + a.z * w.z + a.w * w.w;
                }
                dout[OUT_FC + tid] = acc + bias[j];
            }
            __syncthreads();         // fc path: publish s_tile
        }

        t = s_tile;                  // a sync separated write from this read
        ++it;
    }

    // self-reset: last block out restores counters for the next graph replay.
    if (tid == 0) {
        __threadfence();
        int d = atomicAdd(&g_done, 1);
        if (d == GRID_MAIN - 1) {
            g_ctr  = GRID_MAIN;
            g_done = 0;
            __threadfence();
        }
    }
}

extern "C" void kernel_launch(void* const* d_in, const int* in_sizes, int n_in,
                              void* d_out, int out_size)
{
    const float* gap    = (const float*)d_in[0];
    const float* out1   = (const float*)d_in[1];
    const float* out2   = (const float*)d_in[2];
    const float* out3   = (const float*)d_in[3];
    const float* weight = (const float*)d_in[4];
    const float* bias   = (const float*)d_in[5];
    float* dout = (float*)d_out;

    fused_all_kernel<<<GRID_MAIN, 256>>>(gap, out1, out2, out3, weight, bias, dout);
}